// round 1
// baseline (speedup 1.0000x reference)
#include <cuda_runtime.h>

#define NPTS   8192
#define DM     128
#define DC     64
#define DF     256
#define GRIDS  96
#define NCELLS (96*96*96)
#define CAP    6
#define MK     16
#define WFULL  0xffffffffu

// ---------------- scratch (no allocations allowed) ----------------
__device__ float g_src [NPTS*DM];
__device__ float g_q   [NPTS*DM];
__device__ float g_k   [NPTS*DM];
__device__ float g_v   [NPTS*DM];
__device__ float g_ho  [NPTS*DM];
__device__ float g_tgt [NPTS*DM];
__device__ float g_hid [NPTS*DF];
__device__ float g_fused[NPTS*DC];
__device__ float g_mean[DC];
__device__ float g_var [DC];
__device__ int   g_nbr [NPTS*MK];
__device__ int   g_cnt [NCELLS];
__device__ int   g_cell[NCELLS*CAP];

// ---------------- helpers ----------------
__device__ __forceinline__ float warpAllSum(float v) {
#pragma unroll
    for (int o = 16; o > 0; o >>= 1) v += __shfl_xor_sync(WFULL, v, o);
    return v;
}

// ---------------- grid build ----------------
__global__ void k_clear() {
    int i = blockIdx.x * blockDim.x + threadIdx.x;
    if (i < NCELLS) g_cnt[i] = 0;
}

__global__ void k_scatter(const int* __restrict__ coords, int N) {
    int i = blockIdx.x * blockDim.x + threadIdx.x;
    if (i >= N) return;
    int x = coords[3*i], y = coords[3*i+1], z = coords[3*i+2];
    int cid = (x * GRIDS + y) * GRIDS + z;
    int s = atomicAdd(&g_cnt[cid], 1);
    if (s < CAP) g_cell[cid*CAP + s] = i;
}

// exact jax.lax.top_k(-dist, 16) semantics: sort by (dist, index) ascending
__global__ void k_nbr(const int* __restrict__ coords, int N) {
    int i = blockIdx.x * blockDim.x + threadIdx.x;
    if (i >= N) return;
    int x = coords[3*i], y = coords[3*i+1], z = coords[3*i+2];
    int best[MK];
#pragma unroll
    for (int m = 0; m < MK; m++) best[m] = 0x7fffffff;

    for (int dx = -4; dx <= 4; dx++) {
        int nx = x + dx; if (nx < 0 || nx >= GRIDS) continue;
        int rx = 4 - abs(dx);
        for (int dy = -rx; dy <= rx; dy++) {
            int ny = y + dy; if (ny < 0 || ny >= GRIDS) continue;
            int rz = rx - abs(dy);
            for (int dz = -rz; dz <= rz; dz++) {
                int nz = z + dz; if (nz < 0 || nz >= GRIDS) continue;
                int cid = (nx * GRIDS + ny) * GRIDS + nz;
                int cnt = g_cnt[cid]; if (cnt > CAP) cnt = CAP;
                int d = abs(dx) + abs(dy) + abs(dz);
                for (int s = 0; s < cnt; s++) {
                    int j = g_cell[cid*CAP + s];
                    int key = (d << 13) | j;
                    if (key < best[MK-1]) {
                        best[MK-1] = key;
#pragma unroll
                        for (int m = MK-1; m > 0; m--) {
                            if (best[m] < best[m-1]) {
                                int tmp = best[m-1]; best[m-1] = best[m]; best[m] = tmp;
                            }
                        }
                    }
                }
            }
        }
    }
#pragma unroll
    for (int m = 0; m < MK; m++)
        g_nbr[i*MK + m] = (best[m] == 0x7fffffff) ? -1 : (best[m] & 8191);
}

// ---------------- src = feat@in_w + in_b + PE ----------------
__global__ void k_src(const float* __restrict__ feat, const int* __restrict__ coords,
                      const float* __restrict__ pe_w1, const float* __restrict__ pe_b1,
                      const float* __restrict__ pe_w2, const float* __restrict__ pe_b2,
                      const float* __restrict__ in_w,  const float* __restrict__ in_b) {
    __shared__ float A_s[64*DC];   // features tile
    __shared__ float H_s[64*64];   // PE hidden
    int row0 = blockIdx.x * 64;
    int t = threadIdx.x;           // 128

    for (int idx = t; idx < 64*DC/4; idx += 128)
        ((float4*)A_s)[idx] = __ldg(((const float4*)(feat + row0*DC)) + idx);

    for (int idx = t; idx < 64*64; idx += 128) {
        int r = idx >> 6, hc = idx & 63;
        int gi = row0 + r;
        float vx = (float)coords[3*gi]   * (1.0f/95.0f);
        float vy = (float)coords[3*gi+1] * (1.0f/95.0f);
        float vz = (float)coords[3*gi+2] * (1.0f/95.0f);
        float h = pe_b1[hc] + vx*pe_w1[hc] + vy*pe_w1[64+hc] + vz*pe_w1[128+hc];
        H_s[idx] = fmaxf(h, 0.0f);
    }
    __syncthreads();

    int cg = t & 31, rg = t >> 5;
    int c0 = cg * 4, r0 = rg * 16;
    float acc[16][4];
#pragma unroll
    for (int r = 0; r < 16; r++) { acc[r][0]=acc[r][1]=acc[r][2]=acc[r][3]=0.f; }

#pragma unroll 4
    for (int e = 0; e < DC; e++) {
        float4 w = __ldg((const float4*)(in_w + e*DM + c0));
#pragma unroll
        for (int r = 0; r < 16; r++) {
            float a = A_s[(r0+r)*DC + e];
            acc[r][0] += a*w.x; acc[r][1] += a*w.y; acc[r][2] += a*w.z; acc[r][3] += a*w.w;
        }
    }
#pragma unroll 4
    for (int e = 0; e < 64; e++) {
        float4 w = __ldg((const float4*)(pe_w2 + e*DM + c0));
#pragma unroll
        for (int r = 0; r < 16; r++) {
            float a = H_s[(r0+r)*64 + e];
            acc[r][0] += a*w.x; acc[r][1] += a*w.y; acc[r][2] += a*w.z; acc[r][3] += a*w.w;
        }
    }
    float4 b1 = __ldg((const float4*)(in_b  + c0));
    float4 b2 = __ldg((const float4*)(pe_b2 + c0));
#pragma unroll
    for (int r = 0; r < 16; r++) {
        float4 o = make_float4(acc[r][0]+b1.x+b2.x, acc[r][1]+b1.y+b2.y,
                               acc[r][2]+b1.z+b2.z, acc[r][3]+b1.w+b2.w);
        *(float4*)(g_src + (row0+r0+r)*DM + c0) = o;
    }
}

// ---------------- Q/K/V dense projections ----------------
__device__ __forceinline__ void proj_one(const float* A_s, const float* __restrict__ W,
                                         const float* __restrict__ B, float* Out,
                                         int row0, int r0, int c0) {
    float acc[16][4];
#pragma unroll
    for (int r = 0; r < 16; r++) { acc[r][0]=acc[r][1]=acc[r][2]=acc[r][3]=0.f; }
#pragma unroll 4
    for (int e = 0; e < DM; e++) {
        float4 w = __ldg((const float4*)(W + e*DM + c0));
#pragma unroll
        for (int r = 0; r < 16; r++) {
            float a = A_s[(r0+r)*DM + e];
            acc[r][0] += a*w.x; acc[r][1] += a*w.y; acc[r][2] += a*w.z; acc[r][3] += a*w.w;
        }
    }
    float4 b = __ldg((const float4*)(B + c0));
#pragma unroll
    for (int r = 0; r < 16; r++) {
        float4 o = make_float4(acc[r][0]+b.x, acc[r][1]+b.y, acc[r][2]+b.z, acc[r][3]+b.w);
        *(float4*)(Out + (row0+r0+r)*DM + c0) = o;
    }
}

__global__ void k_proj(const float* __restrict__ qw, const float* __restrict__ qb,
                       const float* __restrict__ kw, const float* __restrict__ kb,
                       const float* __restrict__ vw, const float* __restrict__ vb) {
    __shared__ float A_s[64*DM];
    int row0 = blockIdx.x * 64;
    int t = threadIdx.x;
    for (int idx = t; idx < 64*DM/4; idx += 128)
        ((float4*)A_s)[idx] = *(((const float4*)(g_src + row0*DM)) + idx);
    __syncthreads();
    int cg = t & 31, rg = t >> 5;
    int c0 = cg*4, r0 = rg*16;
    proj_one(A_s, qw, qb, g_q, row0, r0, c0);
    proj_one(A_s, kw, kb, g_k, row0, r0, c0);
    proj_one(A_s, vw, vb, g_v, row0, r0, c0);
}

// ---------------- attention (gather + interleaved-head softmax) ----------------
__global__ void k_attn(const float* __restrict__ kb, const float* __restrict__ vb) {
    int n = blockIdx.x;
    int t = threadIdx.x;           // 128
    int h = t >> 5, lane = t & 31;
    __shared__ float kp[MK][DM];
    __shared__ float vp[MK][DM];

    int j0 = g_nbr[n*MK];
    float qv = (j0 >= 0) ? g_q[j0*DM + t] : 0.f;   // slot0 always valid in practice
#pragma unroll
    for (int m = 0; m < MK; m++) {
        int j = g_nbr[n*MK + m];
        kp[m][t] = (j >= 0) ? g_k[j*DM + t] : __ldg(kb + t);
        vp[m][t] = (j >= 0) ? g_v[j*DM + t] : __ldg(vb + t);
    }
    __syncthreads();

    float sc[MK];
#pragma unroll
    for (int m = 0; m < MK; m++) {
        float p = qv * kp[(h<<2) + (m>>2)][((m&3)<<5) + lane];
        sc[m] = warpAllSum(p) * 0.0883883476483184405f;  // 1/sqrt(128)
    }
    float mx = sc[0];
#pragma unroll
    for (int m = 1; m < MK; m++) mx = fmaxf(mx, sc[m]);
    float se = 0.f;
#pragma unroll
    for (int m = 0; m < MK; m++) { sc[m] = __expf(sc[m] - mx); se += sc[m]; }
    float inv = 1.f / se;
    float o = 0.f;
#pragma unroll
    for (int m = 0; m < MK; m++)
        o += sc[m] * inv * vp[(h<<2) + (m>>2)][((m&3)<<5) + lane];
    g_ho[n*DM + t] = o;
}

// ---------------- out-proj + residual + LN1 ----------------
__global__ void k_oln(const float* __restrict__ ow, const float* __restrict__ ob,
                      const float* __restrict__ n1g, const float* __restrict__ n1b) {
    __shared__ float A_s[64*DM];
    int row0 = blockIdx.x * 64;
    int t = threadIdx.x;
    for (int idx = t; idx < 64*DM/4; idx += 128)
        ((float4*)A_s)[idx] = *(((const float4*)(g_ho + row0*DM)) + idx);
    __syncthreads();
    int cg = t & 31, rg = t >> 5;
    int c0 = cg*4, r0 = rg*16;
    float acc[16][4];
#pragma unroll
    for (int r = 0; r < 16; r++) { acc[r][0]=acc[r][1]=acc[r][2]=acc[r][3]=0.f; }
#pragma unroll 4
    for (int e = 0; e < DM; e++) {
        float4 w = __ldg((const float4*)(ow + e*DM + c0));
#pragma unroll
        for (int r = 0; r < 16; r++) {
            float a = A_s[(r0+r)*DM + e];
            acc[r][0] += a*w.x; acc[r][1] += a*w.y; acc[r][2] += a*w.z; acc[r][3] += a*w.w;
        }
    }
    float4 b  = __ldg((const float4*)(ob  + c0));
    float4 g4 = __ldg((const float4*)(n1g + c0));
    float4 bb = __ldg((const float4*)(n1b + c0));
#pragma unroll
    for (int r = 0; r < 16; r++) {
        int grow = row0 + r0 + r;
        float4 s = *(const float4*)(g_src + grow*DM + c0);
        float v0 = acc[r][0]+b.x+s.x, v1 = acc[r][1]+b.y+s.y;
        float v2 = acc[r][2]+b.z+s.z, v3 = acc[r][3]+b.w+s.w;
        float mean = warpAllSum(v0+v1+v2+v3) * (1.f/128.f);
        float d0=v0-mean, d1=v1-mean, d2=v2-mean, d3=v3-mean;
        float var = warpAllSum(d0*d0+d1*d1+d2*d2+d3*d3) * (1.f/128.f);
        float rs = rsqrtf(var + 1e-5f);
        float4 o = make_float4(d0*rs*g4.x+bb.x, d1*rs*g4.y+bb.y,
                               d2*rs*g4.z+bb.z, d3*rs*g4.w+bb.w);
        *(float4*)(g_tgt + grow*DM + c0) = o;
    }
}

// ---------------- FFN layer 1 (128->256, relu) ----------------
__global__ void k_ffn1(const float* __restrict__ w1, const float* __restrict__ b1) {
    __shared__ float A_s[64*DM];
    int row0 = blockIdx.x * 64;
    int t = threadIdx.x;            // 256
    for (int idx = t; idx < 64*DM/4; idx += 256)
        ((float4*)A_s)[idx] = *(((const float4*)(g_tgt + row0*DM)) + idx);
    __syncthreads();
    int cg = t & 63, rg = t >> 6;   // CG=64, RG=4
    int c0 = cg*4, r0 = rg*16;
    float acc[16][4];
#pragma unroll
    for (int r = 0; r < 16; r++) { acc[r][0]=acc[r][1]=acc[r][2]=acc[r][3]=0.f; }
#pragma unroll 4
    for (int e = 0; e < DM; e++) {
        float4 w = __ldg((const float4*)(w1 + e*DF + c0));
#pragma unroll
        for (int r = 0; r < 16; r++) {
            float a = A_s[(r0+r)*DM + e];
            acc[r][0] += a*w.x; acc[r][1] += a*w.y; acc[r][2] += a*w.z; acc[r][3] += a*w.w;
        }
    }
    float4 b = __ldg((const float4*)(b1 + c0));
#pragma unroll
    for (int r = 0; r < 16; r++) {
        float4 o = make_float4(fmaxf(acc[r][0]+b.x,0.f), fmaxf(acc[r][1]+b.y,0.f),
                               fmaxf(acc[r][2]+b.z,0.f), fmaxf(acc[r][3]+b.w,0.f));
        *(float4*)(g_hid + (row0+r0+r)*DF + c0) = o;
    }
}

// ---------------- FFN layer 2 + residual + LN3 ----------------
__global__ void k_ffn2(const float* __restrict__ w2, const float* __restrict__ b2,
                       const float* __restrict__ n3g, const float* __restrict__ n3b) {
    __shared__ float A_s[32*DF];
    int row0 = blockIdx.x * 32;
    int t = threadIdx.x;            // 128
    for (int idx = t; idx < 32*DF/4; idx += 128)
        ((float4*)A_s)[idx] = *(((const float4*)(g_hid + row0*DF)) + idx);
    __syncthreads();
    int cg = t & 31, rg = t >> 5;   // CG=32, RG=4, RPT=8
    int c0 = cg*4, r0 = rg*8;
    float acc[8][4];
#pragma unroll
    for (int r = 0; r < 8; r++) { acc[r][0]=acc[r][1]=acc[r][2]=acc[r][3]=0.f; }
#pragma unroll 4
    for (int e = 0; e < DF; e++) {
        float4 w = __ldg((const float4*)(w2 + e*DM + c0));
#pragma unroll
        for (int r = 0; r < 8; r++) {
            float a = A_s[(r0+r)*DF + e];
            acc[r][0] += a*w.x; acc[r][1] += a*w.y; acc[r][2] += a*w.z; acc[r][3] += a*w.w;
        }
    }
    float4 b  = __ldg((const float4*)(b2  + c0));
    float4 g4 = __ldg((const float4*)(n3g + c0));
    float4 bb = __ldg((const float4*)(n3b + c0));
#pragma unroll
    for (int r = 0; r < 8; r++) {
        int grow = row0 + r0 + r;
        float4 s = *(const float4*)(g_tgt + grow*DM + c0);
        float v0 = acc[r][0]+b.x+s.x, v1 = acc[r][1]+b.y+s.y;
        float v2 = acc[r][2]+b.z+s.z, v3 = acc[r][3]+b.w+s.w;
        float mean = warpAllSum(v0+v1+v2+v3) * (1.f/128.f);
        float d0=v0-mean, d1=v1-mean, d2=v2-mean, d3=v3-mean;
        float var = warpAllSum(d0*d0+d1*d1+d2*d2+d3*d3) * (1.f/128.f);
        float rs = rsqrtf(var + 1e-5f);
        float4 o = make_float4(d0*rs*g4.x+bb.x, d1*rs*g4.y+bb.y,
                               d2*rs*g4.z+bb.z, d3*rs*g4.w+bb.w);
        *(float4*)(g_tgt + grow*DM + c0) = o;
    }
}

// ---------------- fusion GEMM: concat(feat, tgt) @ fu_w + fu_b ----------------
__global__ void k_fuse(const float* __restrict__ feat,
                       const float* __restrict__ fw, const float* __restrict__ fb) {
    __shared__ float A_s[32*192];
    int row0 = blockIdx.x * 32;
    int t = threadIdx.x;            // 128
    for (int idx = t; idx < 32*16; idx += 128) {      // features part (64 cols = 16 f4)
        int r = idx >> 4, c4 = idx & 15;
        *(float4*)(A_s + r*192 + c4*4) = __ldg((const float4*)(feat + (row0+r)*DC + c4*4));
    }
    for (int idx = t; idx < 32*32; idx += 128) {      // tgt part (128 cols = 32 f4)
        int r = idx >> 5, c4 = idx & 31;
        *(float4*)(A_s + r*192 + 64 + c4*4) = *(const float4*)(g_tgt + (row0+r)*DM + c4*4);
    }
    __syncthreads();
    int cg = t & 15, rg = t >> 4;   // CG=16, RG=8, RPT=4
    int c0 = cg*4, r0 = rg*4;
    float acc[4][4];
#pragma unroll
    for (int r = 0; r < 4; r++) { acc[r][0]=acc[r][1]=acc[r][2]=acc[r][3]=0.f; }
#pragma unroll 4
    for (int e = 0; e < 192; e++) {
        float4 w = __ldg((const float4*)(fw + e*DC + c0));
#pragma unroll
        for (int r = 0; r < 4; r++) {
            float a = A_s[(r0+r)*192 + e];
            acc[r][0] += a*w.x; acc[r][1] += a*w.y; acc[r][2] += a*w.z; acc[r][3] += a*w.w;
        }
    }
    float4 b = __ldg((const float4*)(fb + c0));
#pragma unroll
    for (int r = 0; r < 4; r++) {
        float4 o = make_float4(acc[r][0]+b.x, acc[r][1]+b.y, acc[r][2]+b.z, acc[r][3]+b.w);
        *(float4*)(g_fused + (row0+r0+r)*DC + c0) = o;
    }
}

// ---------------- batchnorm stats (train mode, biased var) ----------------
__global__ void k_stats(int N) {
    int c = blockIdx.x;             // 64 blocks
    int t = threadIdx.x;            // 256
    float s = 0.f, q = 0.f;
    for (int r = t; r < N; r += 256) {
        float v = g_fused[r*DC + c];
        s += v; q += v*v;
    }
    __shared__ float ss[256], sq[256];
    ss[t] = s; sq[t] = q; __syncthreads();
    for (int st = 128; st > 0; st >>= 1) {
        if (t < st) { ss[t] += ss[t+st]; sq[t] += sq[t+st]; }
        __syncthreads();
    }
    if (t == 0) {
        float mean = ss[0] / (float)N;
        g_mean[c] = mean;
        g_var[c]  = sq[0] / (float)N - mean*mean;
    }
}

__global__ void k_out(const float* __restrict__ bng, const float* __restrict__ bnb,
                      float* __restrict__ out, int total) {
    for (int i = blockIdx.x*blockDim.x + threadIdx.x; i < total; i += gridDim.x*blockDim.x) {
        int c = i & (DC-1);
        float v = g_fused[i];
        v = (v - g_mean[c]) * rsqrtf(g_var[c] + 1e-3f) * bng[c] + bnb[c];
        out[i] = fmaxf(v, 0.f);
    }
}

// ---------------- launch ----------------
extern "C" void kernel_launch(void* const* d_in, const int* in_sizes, int n_in,
                              void* d_out, int out_size) {
    const float* feat   = (const float*)d_in[0];
    const int*   coords = (const int*)  d_in[1];
    const float* pe_w1  = (const float*)d_in[2];
    const float* pe_b1  = (const float*)d_in[3];
    const float* pe_w2  = (const float*)d_in[4];
    const float* pe_b2  = (const float*)d_in[5];
    const float* in_w   = (const float*)d_in[6];
    const float* in_b   = (const float*)d_in[7];
    const float* q_w    = (const float*)d_in[8];
    const float* q_b    = (const float*)d_in[9];
    const float* k_w    = (const float*)d_in[10];
    const float* k_b    = (const float*)d_in[11];
    const float* v_w    = (const float*)d_in[12];
    const float* v_b    = (const float*)d_in[13];
    const float* o_w    = (const float*)d_in[14];
    const float* o_b    = (const float*)d_in[15];
    const float* n1_g   = (const float*)d_in[16];
    const float* n1_b   = (const float*)d_in[17];
    const float* l1_w   = (const float*)d_in[18];
    const float* l1_b   = (const float*)d_in[19];
    const float* l2_w   = (const float*)d_in[20];
    const float* l2_b   = (const float*)d_in[21];
    const float* n3_g   = (const float*)d_in[22];
    const float* n3_b   = (const float*)d_in[23];
    const float* fu_w   = (const float*)d_in[24];
    const float* fu_b   = (const float*)d_in[25];
    const float* bn_g   = (const float*)d_in[26];
    const float* bn_b   = (const float*)d_in[27];
    float* out = (float*)d_out;

    int N = in_sizes[0] / DC;   // 8192

    k_clear  <<<(NCELLS+1023)/1024, 1024>>>();
    k_scatter<<<(N+255)/256, 256>>>(coords, N);
    k_nbr    <<<(N+255)/256, 256>>>(coords, N);
    k_src    <<<N/64, 128>>>(feat, coords, pe_w1, pe_b1, pe_w2, pe_b2, in_w, in_b);
    k_proj   <<<N/64, 128>>>(q_w, q_b, k_w, k_b, v_w, v_b);
    k_attn   <<<N, 128>>>(k_b, v_b);
    k_oln    <<<N/64, 128>>>(o_w, o_b, n1_g, n1_b);
    k_ffn1   <<<N/64, 256>>>(l1_w, l1_b);
    k_ffn2   <<<N/32, 128>>>(l2_w, l2_b, n3_g, n3_b);
    k_fuse   <<<N/32, 128>>>(feat, fu_w, fu_b);
    k_stats  <<<DC, 256>>>(N);
    k_out    <<<256, 256>>>(bn_g, bn_b, out, N*DC);
}

// round 2
// speedup vs baseline: 1.3850x; 1.3850x over previous
#include <cuda_runtime.h>

#define NPTS   8192
#define DM     128
#define DC     64
#define DF     256
#define GRIDS  96
#define NCELLS (96*96*96)
#define CAP    6
#define MK     16
#define WFULL  0xffffffffu

// ---------------- scratch (no allocations allowed) ----------------
__device__ float g_src [NPTS*DM];
__device__ float g_q   [NPTS*DM];
__device__ float g_k   [NPTS*DM];
__device__ float g_v   [NPTS*DM];
__device__ float g_ho  [NPTS*DM];
__device__ float g_fused[NPTS*DC];
__device__ float g_mean[DC];
__device__ float g_var [DC];
__device__ int   g_nbr [NPTS*MK];
__device__ int   g_cnt [NCELLS];
__device__ int   g_cell[NCELLS*CAP];

// ---------------- helpers ----------------
__device__ __forceinline__ float warpAllSum(float v) {
#pragma unroll
    for (int o = 16; o > 0; o >>= 1) v += __shfl_xor_sync(WFULL, v, o);
    return v;
}

// ---------------- grid build ----------------
__global__ void k_clear() {
    int i = blockIdx.x * blockDim.x + threadIdx.x;
    if (i < NCELLS) g_cnt[i] = 0;
}

__global__ void k_scatter(const int* __restrict__ coords, int N) {
    int i = blockIdx.x * blockDim.x + threadIdx.x;
    if (i >= N) return;
    int x = coords[3*i], y = coords[3*i+1], z = coords[3*i+2];
    int cid = (x * GRIDS + y) * GRIDS + z;
    int s = atomicAdd(&g_cnt[cid], 1);
    if (s < CAP) g_cell[cid*CAP + s] = i;
}

// exact jax.lax.top_k(-dist, 16) semantics: sort by (dist, index) ascending
__global__ void k_nbr(const int* __restrict__ coords, int N) {
    int i = blockIdx.x * blockDim.x + threadIdx.x;
    if (i >= N) return;
    int x = coords[3*i], y = coords[3*i+1], z = coords[3*i+2];
    int best[MK];
#pragma unroll
    for (int m = 0; m < MK; m++) best[m] = 0x7fffffff;

    for (int dx = -4; dx <= 4; dx++) {
        int nx = x + dx; if (nx < 0 || nx >= GRIDS) continue;
        int rx = 4 - abs(dx);
        for (int dy = -rx; dy <= rx; dy++) {
            int ny = y + dy; if (ny < 0 || ny >= GRIDS) continue;
            int rz = rx - abs(dy);
            for (int dz = -rz; dz <= rz; dz++) {
                int nz = z + dz; if (nz < 0 || nz >= GRIDS) continue;
                int cid = (nx * GRIDS + ny) * GRIDS + nz;
                int cnt = g_cnt[cid]; if (cnt > CAP) cnt = CAP;
                int d = abs(dx) + abs(dy) + abs(dz);
                for (int s = 0; s < cnt; s++) {
                    int j = g_cell[cid*CAP + s];
                    int key = (d << 13) | j;
                    if (key < best[MK-1]) {
                        best[MK-1] = key;
#pragma unroll
                        for (int m = MK-1; m > 0; m--) {
                            if (best[m] < best[m-1]) {
                                int tmp = best[m-1]; best[m-1] = best[m]; best[m] = tmp;
                            }
                        }
                    }
                }
            }
        }
    }
#pragma unroll
    for (int m = 0; m < MK; m++)
        g_nbr[i*MK + m] = (best[m] == 0x7fffffff) ? -1 : (best[m] & 8191);
}

// ---------------- fused src(+PE) -> q/k/v, 32-row tiles, 256 threads ------
__device__ __forceinline__ void proj32(const float* __restrict__ S,
                                       const float* __restrict__ W,
                                       const float* __restrict__ B,
                                       float* __restrict__ Out,
                                       int row0, int r0, int c0) {
    float acc[4][4];
#pragma unroll
    for (int r = 0; r < 4; r++) { acc[r][0]=acc[r][1]=acc[r][2]=acc[r][3]=0.f; }
#pragma unroll 8
    for (int e = 0; e < DM; e++) {
        float4 w = __ldg((const float4*)(W + e*DM + c0));
#pragma unroll
        for (int r = 0; r < 4; r++) {
            float a = S[(r0+r)*DM + e];
            acc[r][0] += a*w.x; acc[r][1] += a*w.y; acc[r][2] += a*w.z; acc[r][3] += a*w.w;
        }
    }
    float4 b = __ldg((const float4*)(B + c0));
#pragma unroll
    for (int r = 0; r < 4; r++) {
        float4 o = make_float4(acc[r][0]+b.x, acc[r][1]+b.y, acc[r][2]+b.z, acc[r][3]+b.w);
        *(float4*)(Out + (row0+r0+r)*DM + c0) = o;
    }
}

__global__ __launch_bounds__(256)
void k_srcproj(const float* __restrict__ feat, const int* __restrict__ coords,
               const float* __restrict__ pe_w1, const float* __restrict__ pe_b1,
               const float* __restrict__ pe_w2, const float* __restrict__ pe_b2,
               const float* __restrict__ in_w,  const float* __restrict__ in_b,
               const float* __restrict__ qw, const float* __restrict__ qb,
               const float* __restrict__ kw, const float* __restrict__ kb,
               const float* __restrict__ vw, const float* __restrict__ vb) {
    __shared__ float F[32*DC];     // features tile
    __shared__ float H[32*64];     // PE hidden
    __shared__ float S[32*DM];     // src tile
    int row0 = blockIdx.x * 32;
    int t = threadIdx.x;

    for (int i = t; i < 32*DC/4; i += 256)
        ((float4*)F)[i] = __ldg(((const float4*)(feat + row0*DC)) + i);
    for (int i = t; i < 32*64; i += 256) {
        int r = i >> 6, hc = i & 63;
        int gi = row0 + r;
        float vx = (float)coords[3*gi]   * (1.0f/95.0f);
        float vy = (float)coords[3*gi+1] * (1.0f/95.0f);
        float vz = (float)coords[3*gi+2] * (1.0f/95.0f);
        float h = pe_b1[hc] + vx*pe_w1[hc] + vy*pe_w1[64+hc] + vz*pe_w1[128+hc];
        H[i] = fmaxf(h, 0.0f);
    }
    __syncthreads();

    int cg = t & 31, rg = t >> 5;
    int c0 = cg * 4, r0 = rg * 4;
    {
        float acc[4][4];
#pragma unroll
        for (int r = 0; r < 4; r++) { acc[r][0]=acc[r][1]=acc[r][2]=acc[r][3]=0.f; }
#pragma unroll 8
        for (int e = 0; e < DC; e++) {
            float4 w = __ldg((const float4*)(in_w + e*DM + c0));
#pragma unroll
            for (int r = 0; r < 4; r++) {
                float a = F[(r0+r)*DC + e];
                acc[r][0] += a*w.x; acc[r][1] += a*w.y; acc[r][2] += a*w.z; acc[r][3] += a*w.w;
            }
        }
#pragma unroll 8
        for (int e = 0; e < 64; e++) {
            float4 w = __ldg((const float4*)(pe_w2 + e*DM + c0));
#pragma unroll
            for (int r = 0; r < 4; r++) {
                float a = H[(r0+r)*64 + e];
                acc[r][0] += a*w.x; acc[r][1] += a*w.y; acc[r][2] += a*w.z; acc[r][3] += a*w.w;
            }
        }
        float4 b1 = __ldg((const float4*)(in_b  + c0));
        float4 b2 = __ldg((const float4*)(pe_b2 + c0));
#pragma unroll
        for (int r = 0; r < 4; r++) {
            float4 o = make_float4(acc[r][0]+b1.x+b2.x, acc[r][1]+b1.y+b2.y,
                                   acc[r][2]+b1.z+b2.z, acc[r][3]+b1.w+b2.w);
            S[(r0+r)*DM + c0+0] = o.x; S[(r0+r)*DM + c0+1] = o.y;
            S[(r0+r)*DM + c0+2] = o.z; S[(r0+r)*DM + c0+3] = o.w;
            *(float4*)(g_src + (row0+r0+r)*DM + c0) = o;
        }
    }
    __syncthreads();
    proj32(S, qw, qb, g_q, row0, r0, c0);
    proj32(S, kw, kb, g_k, row0, r0, c0);
    proj32(S, vw, vb, g_v, row0, r0, c0);
}

// ---------------- attention (gather + interleaved-head softmax) ----------------
__global__ void k_attn(const float* __restrict__ kb, const float* __restrict__ vb) {
    int n = blockIdx.x;
    int t = threadIdx.x;           // 128
    int h = t >> 5, lane = t & 31;
    __shared__ float kp[MK][DM];
    __shared__ float vp[MK][DM];

    float kbv = __ldg(kb + t), vbv = __ldg(vb + t);
    int j0 = g_nbr[n*MK];
    float qv = (j0 >= 0) ? g_q[j0*DM + t] : 0.f;
#pragma unroll
    for (int m = 0; m < MK; m++) {
        int j = g_nbr[n*MK + m];
        kp[m][t] = (j >= 0) ? g_k[j*DM + t] : kbv;
        vp[m][t] = (j >= 0) ? g_v[j*DM + t] : vbv;
    }
    __syncthreads();

    float sc[MK];
#pragma unroll
    for (int m = 0; m < MK; m++) {
        float p = qv * kp[(h<<2) + (m>>2)][((m&3)<<5) + lane];
        sc[m] = warpAllSum(p) * 0.0883883476483184405f;  // 1/sqrt(128)
    }
    float mx = sc[0];
#pragma unroll
    for (int m = 1; m < MK; m++) mx = fmaxf(mx, sc[m]);
    float se = 0.f;
#pragma unroll
    for (int m = 0; m < MK; m++) { sc[m] = __expf(sc[m] - mx); se += sc[m]; }
    float inv = 1.f / se;
    float o = 0.f;
#pragma unroll
    for (int m = 0; m < MK; m++)
        o += sc[m] * inv * vp[(h<<2) + (m>>2)][((m&3)<<5) + lane];
    g_ho[n*DM + t] = o;
}

// ------- mega kernel: o-proj + LN1 + FFN1 + FFN2 + LN3 + fusion GEMM -------
__global__ __launch_bounds__(256)
void k_mega(const float* __restrict__ ow, const float* __restrict__ ob,
            const float* __restrict__ n1g, const float* __restrict__ n1b,
            const float* __restrict__ w1, const float* __restrict__ b1,
            const float* __restrict__ w2, const float* __restrict__ b2,
            const float* __restrict__ n3g, const float* __restrict__ n3b,
            const float* __restrict__ feat,
            const float* __restrict__ fw, const float* __restrict__ fb) {
    __shared__ float T[32*DM];     // tgt tile
    __shared__ float U[32*DF];     // stage1 input (first half) / ffn hidden
    __shared__ float F[32*DC];     // features tile
    int row0 = blockIdx.x * 32;
    int t = threadIdx.x;

    for (int i = t; i < 32*DM/4; i += 256)
        ((float4*)U)[i] = *(((const float4*)(g_ho + row0*DM)) + i);
    for (int i = t; i < 32*DC/4; i += 256)
        ((float4*)F)[i] = __ldg(((const float4*)(feat + row0*DC)) + i);
    __syncthreads();

    // ---- stage 1: out-proj + residual(src) + LN1 -> T ----
    {
        int cg = t & 31, rg = t >> 5;
        int c0 = cg*4, r0 = rg*4;
        float acc[4][4];
#pragma unroll
        for (int r = 0; r < 4; r++) { acc[r][0]=acc[r][1]=acc[r][2]=acc[r][3]=0.f; }
#pragma unroll 8
        for (int e = 0; e < DM; e++) {
            float4 w = __ldg((const float4*)(ow + e*DM + c0));
#pragma unroll
            for (int r = 0; r < 4; r++) {
                float a = U[(r0+r)*DM + e];
                acc[r][0] += a*w.x; acc[r][1] += a*w.y; acc[r][2] += a*w.z; acc[r][3] += a*w.w;
            }
        }
        float4 b  = __ldg((const float4*)(ob  + c0));
        float4 g4 = __ldg((const float4*)(n1g + c0));
        float4 bb = __ldg((const float4*)(n1b + c0));
#pragma unroll
        for (int r = 0; r < 4; r++) {
            float4 s = *(const float4*)(g_src + (row0+r0+r)*DM + c0);
            float v0 = acc[r][0]+b.x+s.x, v1 = acc[r][1]+b.y+s.y;
            float v2 = acc[r][2]+b.z+s.z, v3 = acc[r][3]+b.w+s.w;
            float mean = warpAllSum(v0+v1+v2+v3) * (1.f/128.f);
            float d0=v0-mean, d1=v1-mean, d2=v2-mean, d3=v3-mean;
            float var = warpAllSum(d0*d0+d1*d1+d2*d2+d3*d3) * (1.f/128.f);
            float rs = rsqrtf(var + 1e-5f);
            float* tp = T + (r0+r)*DM + c0;
            tp[0]=d0*rs*g4.x+bb.x; tp[1]=d1*rs*g4.y+bb.y;
            tp[2]=d2*rs*g4.z+bb.z; tp[3]=d3*rs*g4.w+bb.w;
        }
    }
    __syncthreads();

    // ---- stage 2: FFN1 (128->256, relu) -> U ----
    {
        int cg = t & 63, rg = t >> 6;
        int c0 = cg*4, r0 = rg*8;
        float acc[8][4];
#pragma unroll
        for (int r = 0; r < 8; r++) { acc[r][0]=acc[r][1]=acc[r][2]=acc[r][3]=0.f; }
#pragma unroll 8
        for (int e = 0; e < DM; e++) {
            float4 w = __ldg((const float4*)(w1 + e*DF + c0));
#pragma unroll
            for (int r = 0; r < 8; r++) {
                float a = T[(r0+r)*DM + e];
                acc[r][0] += a*w.x; acc[r][1] += a*w.y; acc[r][2] += a*w.z; acc[r][3] += a*w.w;
            }
        }
        float4 b = __ldg((const float4*)(b1 + c0));
#pragma unroll
        for (int r = 0; r < 8; r++) {
            float* up = U + (r0+r)*DF + c0;
            up[0]=fmaxf(acc[r][0]+b.x,0.f); up[1]=fmaxf(acc[r][1]+b.y,0.f);
            up[2]=fmaxf(acc[r][2]+b.z,0.f); up[3]=fmaxf(acc[r][3]+b.w,0.f);
        }
    }
    __syncthreads();

    // ---- stage 3: FFN2 (256->128) + residual(T) + LN3 -> T ----
    {
        int cg = t & 31, rg = t >> 5;
        int c0 = cg*4, r0 = rg*4;
        float acc[4][4];
#pragma unroll
        for (int r = 0; r < 4; r++) { acc[r][0]=acc[r][1]=acc[r][2]=acc[r][3]=0.f; }
#pragma unroll 8
        for (int e = 0; e < DF; e++) {
            float4 w = __ldg((const float4*)(w2 + e*DM + c0));
#pragma unroll
            for (int r = 0; r < 4; r++) {
                float a = U[(r0+r)*DF + e];
                acc[r][0] += a*w.x; acc[r][1] += a*w.y; acc[r][2] += a*w.z; acc[r][3] += a*w.w;
            }
        }
        float4 b  = __ldg((const float4*)(b2  + c0));
        float4 g4 = __ldg((const float4*)(n3g + c0));
        float4 bb = __ldg((const float4*)(n3b + c0));
#pragma unroll
        for (int r = 0; r < 4; r++) {
            float* tp = T + (r0+r)*DM + c0;
            float v0 = acc[r][0]+b.x+tp[0], v1 = acc[r][1]+b.y+tp[1];
            float v2 = acc[r][2]+b.z+tp[2], v3 = acc[r][3]+b.w+tp[3];
            float mean = warpAllSum(v0+v1+v2+v3) * (1.f/128.f);
            float d0=v0-mean, d1=v1-mean, d2=v2-mean, d3=v3-mean;
            float var = warpAllSum(d0*d0+d1*d1+d2*d2+d3*d3) * (1.f/128.f);
            float rs = rsqrtf(var + 1e-5f);
            tp[0]=d0*rs*g4.x+bb.x; tp[1]=d1*rs*g4.y+bb.y;
            tp[2]=d2*rs*g4.z+bb.z; tp[3]=d3*rs*g4.w+bb.w;
        }
    }
    __syncthreads();

    // ---- stage 4: fusion GEMM concat(F, T) @ fw + fb -> g_fused ----
    {
        int cg = t & 15, rg = t >> 4;
        int c0 = cg*4, r0 = rg*2;
        float acc[2][4];
#pragma unroll
        for (int r = 0; r < 2; r++) { acc[r][0]=acc[r][1]=acc[r][2]=acc[r][3]=0.f; }
#pragma unroll 8
        for (int e = 0; e < DC; e++) {
            float4 w = __ldg((const float4*)(fw + e*DC + c0));
#pragma unroll
            for (int r = 0; r < 2; r++) {
                float a = F[(r0+r)*DC + e];
                acc[r][0] += a*w.x; acc[r][1] += a*w.y; acc[r][2] += a*w.z; acc[r][3] += a*w.w;
            }
        }
#pragma unroll 8
        for (int e = 0; e < DM; e++) {
            float4 w = __ldg((const float4*)(fw + (DC+e)*DC + c0));
#pragma unroll
            for (int r = 0; r < 2; r++) {
                float a = T[(r0+r)*DM + e];
                acc[r][0] += a*w.x; acc[r][1] += a*w.y; acc[r][2] += a*w.z; acc[r][3] += a*w.w;
            }
        }
        float4 b = __ldg((const float4*)(fb + c0));
#pragma unroll
        for (int r = 0; r < 2; r++) {
            float4 o = make_float4(acc[r][0]+b.x, acc[r][1]+b.y, acc[r][2]+b.z, acc[r][3]+b.w);
            *(float4*)(g_fused + (row0+r0+r)*DC + c0) = o;
        }
    }
}

// ---------------- batchnorm stats (train mode, biased var) ----------------
__global__ void k_stats(int N) {
    int c = blockIdx.x;             // 64 blocks
    int t = threadIdx.x;            // 256
    float s = 0.f, q = 0.f;
    for (int r = t; r < N; r += 256) {
        float v = g_fused[r*DC + c];
        s += v; q += v*v;
    }
    __shared__ float ss[256], sq[256];
    ss[t] = s; sq[t] = q; __syncthreads();
    for (int st = 128; st > 0; st >>= 1) {
        if (t < st) { ss[t] += ss[t+st]; sq[t] += sq[t+st]; }
        __syncthreads();
    }
    if (t == 0) {
        float mean = ss[0] / (float)N;
        g_mean[c] = mean;
        g_var[c]  = sq[0] / (float)N - mean*mean;
    }
}

__global__ void k_out(const float* __restrict__ bng, const float* __restrict__ bnb,
                      float* __restrict__ out, int total) {
    for (int i = blockIdx.x*blockDim.x + threadIdx.x; i < total; i += gridDim.x*blockDim.x) {
        int c = i & (DC-1);
        float v = g_fused[i];
        v = (v - g_mean[c]) * rsqrtf(g_var[c] + 1e-3f) * bng[c] + bnb[c];
        out[i] = fmaxf(v, 0.f);
    }
}

// ---------------- launch ----------------
extern "C" void kernel_launch(void* const* d_in, const int* in_sizes, int n_in,
                              void* d_out, int out_size) {
    const float* feat   = (const float*)d_in[0];
    const int*   coords = (const int*)  d_in[1];
    const float* pe_w1  = (const float*)d_in[2];
    const float* pe_b1  = (const float*)d_in[3];
    const float* pe_w2  = (const float*)d_in[4];
    const float* pe_b2  = (const float*)d_in[5];
    const float* in_w   = (const float*)d_in[6];
    const float* in_b   = (const float*)d_in[7];
    const float* q_w    = (const float*)d_in[8];
    const float* q_b    = (const float*)d_in[9];
    const float* k_w    = (const float*)d_in[10];
    const float* k_b    = (const float*)d_in[11];
    const float* v_w    = (const float*)d_in[12];
    const float* v_b    = (const float*)d_in[13];
    const float* o_w    = (const float*)d_in[14];
    const float* o_b    = (const float*)d_in[15];
    const float* n1_g   = (const float*)d_in[16];
    const float* n1_b   = (const float*)d_in[17];
    const float* l1_w   = (const float*)d_in[18];
    const float* l1_b   = (const float*)d_in[19];
    const float* l2_w   = (const float*)d_in[20];
    const float* l2_b   = (const float*)d_in[21];
    const float* n3_g   = (const float*)d_in[22];
    const float* n3_b   = (const float*)d_in[23];
    const float* fu_w   = (const float*)d_in[24];
    const float* fu_b   = (const float*)d_in[25];
    const float* bn_g   = (const float*)d_in[26];
    const float* bn_b   = (const float*)d_in[27];
    float* out = (float*)d_out;

    int N = in_sizes[0] / DC;   // 8192

    k_clear  <<<(NCELLS+1023)/1024, 1024>>>();
    k_scatter<<<(N+255)/256, 256>>>(coords, N);
    k_nbr    <<<(N+63)/64, 64>>>(coords, N);
    k_srcproj<<<N/32, 256>>>(feat, coords, pe_w1, pe_b1, pe_w2, pe_b2, in_w, in_b,
                             q_w, q_b, k_w, k_b, v_w, v_b);
    k_attn   <<<N, 128>>>(k_b, v_b);
    k_mega   <<<N/32, 256>>>(o_w, o_b, n1_g, n1_b, l1_w, l1_b, l2_w, l2_b,
                             n3_g, n3_b, feat, fu_w, fu_b);
    k_stats  <<<DC, 256>>>(N);
    k_out    <<<256, 256>>>(bn_g, bn_b, out, N*DC);
}

// round 3
// speedup vs baseline: 1.5138x; 1.0930x over previous
#include <cuda_runtime.h>

#define NPTS   8192
#define DM     128
#define DC     64
#define DF     256
#define GRIDS  96
#define NCELLS (96*96*96)
#define CAP    6
#define MK     16
#define WFULL  0xffffffffu

typedef unsigned long long u64;

// ---------------- scratch (no allocations allowed) ----------------
__device__ float g_src [NPTS*DM];
__device__ float g_q   [NPTS*DM];
__device__ float g_k   [NPTS*DM];
__device__ float g_v   [NPTS*DM];
__device__ float g_ho  [NPTS*DM];
__device__ float g_fused[NPTS*DC];
__device__ float g_mean[DC];
__device__ float g_var [DC];
__device__ int   g_nbr [NPTS*MK];
__device__ int   g_cnt [NCELLS];
__device__ int   g_cell[NCELLS*CAP];

// ---------------- packed fp32x2 helpers ----------------
__device__ __forceinline__ u64 pk2(float a, float b) {
    u64 r; asm("mov.b64 %0,{%1,%2};" : "=l"(r) : "f"(a), "f"(b)); return r;
}
__device__ __forceinline__ void upk2(u64 v, float& a, float& b) {
    asm("mov.b64 {%0,%1},%2;" : "=f"(a), "=f"(b) : "l"(v));
}
__device__ __forceinline__ void fma2(u64& d, u64 a, u64 b) {
    asm("fma.rn.f32x2 %0,%1,%2,%0;" : "+l"(d) : "l"(a), "l"(b));
}

__device__ __forceinline__ float warpAllSum(float v) {
#pragma unroll
    for (int o = 16; o > 0; o >>= 1) v += __shfl_xor_sync(WFULL, v, o);
    return v;
}

// single-weight-stream tile accumulate: ROWS x 4 cols, packed fma2
template<int ROWS, int K, int LDA>
__device__ __forceinline__ void gacc(const float* __restrict__ A,
                                     const float* __restrict__ W, int ldw, int c0,
                                     u64* a01, u64* a23) {
#pragma unroll 2
    for (int e0 = 0; e0 < K; e0 += 4) {
        float4 av[ROWS];
#pragma unroll
        for (int r = 0; r < ROWS; r++)
            av[r] = *(const float4*)(A + r*LDA + e0);
#pragma unroll
        for (int ee = 0; ee < 4; ee++) {
            double2 wd = __ldg((const double2*)(W + (e0+ee)*ldw + c0));
            u64 w01 = __double_as_longlong(wd.x), w23 = __double_as_longlong(wd.y);
#pragma unroll
            for (int r = 0; r < ROWS; r++) {
                float x = (ee==0)?av[r].x:(ee==1)?av[r].y:(ee==2)?av[r].z:av[r].w;
                u64 a2 = pk2(x, x);
                fma2(a01[r], a2, w01); fma2(a23[r], a2, w23);
            }
        }
    }
}

// ---------------- grid build ----------------
__global__ void k_clear() {
    int i = blockIdx.x * blockDim.x + threadIdx.x;
    if (i < NCELLS) g_cnt[i] = 0;
}

__global__ void k_scatter(const int* __restrict__ coords, int N) {
    int i = blockIdx.x * blockDim.x + threadIdx.x;
    if (i >= N) return;
    int x = coords[3*i], y = coords[3*i+1], z = coords[3*i+2];
    int cid = (x * GRIDS + y) * GRIDS + z;
    int s = atomicAdd(&g_cnt[cid], 1);
    if (s < CAP) g_cell[cid*CAP + s] = i;
}

// exact jax.lax.top_k(-dist, 16) semantics: sort by (dist, index) ascending
__global__ void k_nbr(const int* __restrict__ coords, int N) {
    int i = blockIdx.x * blockDim.x + threadIdx.x;
    if (i >= N) return;
    int x = coords[3*i], y = coords[3*i+1], z = coords[3*i+2];
    int best[MK];
#pragma unroll
    for (int m = 0; m < MK; m++) best[m] = 0x7fffffff;

    for (int dx = -4; dx <= 4; dx++) {
        int nx = x + dx; if (nx < 0 || nx >= GRIDS) continue;
        int rx = 4 - abs(dx);
        for (int dy = -rx; dy <= rx; dy++) {
            int ny = y + dy; if (ny < 0 || ny >= GRIDS) continue;
            int rz = rx - abs(dy);
            for (int dz = -rz; dz <= rz; dz++) {
                int nz = z + dz; if (nz < 0 || nz >= GRIDS) continue;
                int cid = (nx * GRIDS + ny) * GRIDS + nz;
                int cnt = g_cnt[cid]; if (cnt > CAP) cnt = CAP;
                int d = abs(dx) + abs(dy) + abs(dz);
                for (int s = 0; s < cnt; s++) {
                    int j = g_cell[cid*CAP + s];
                    int key = (d << 13) | j;
                    if (key < best[MK-1]) {
                        best[MK-1] = key;
#pragma unroll
                        for (int m = MK-1; m > 0; m--) {
                            if (best[m] < best[m-1]) {
                                int tmp = best[m-1]; best[m-1] = best[m]; best[m] = tmp;
                            }
                        }
                    }
                }
            }
        }
    }
#pragma unroll
    for (int m = 0; m < MK; m++)
        g_nbr[i*MK + m] = (best[m] == 0x7fffffff) ? -1 : (best[m] & 8191);
}

// ---------------- fused src(+PE) -> q/k/v ----------------
__global__ __launch_bounds__(256)
void k_srcproj(const float* __restrict__ feat, const int* __restrict__ coords,
               const float* __restrict__ pe_w1, const float* __restrict__ pe_b1,
               const float* __restrict__ pe_w2, const float* __restrict__ pe_b2,
               const float* __restrict__ in_w,  const float* __restrict__ in_b,
               const float* __restrict__ qw, const float* __restrict__ qb,
               const float* __restrict__ kw, const float* __restrict__ kb,
               const float* __restrict__ vw, const float* __restrict__ vb) {
    __shared__ float F[32*DC];
    __shared__ float H[32*64];
    __shared__ float S[32*DM];
    int row0 = blockIdx.x * 32;
    int t = threadIdx.x;

    for (int i = t; i < 32*DC/4; i += 256)
        ((float4*)F)[i] = __ldg(((const float4*)(feat + row0*DC)) + i);
    for (int i = t; i < 32*64; i += 256) {
        int r = i >> 6, hc = i & 63;
        int gi = row0 + r;
        float vx = (float)coords[3*gi]   * (1.0f/95.0f);
        float vy = (float)coords[3*gi+1] * (1.0f/95.0f);
        float vz = (float)coords[3*gi+2] * (1.0f/95.0f);
        float h = pe_b1[hc] + vx*pe_w1[hc] + vy*pe_w1[64+hc] + vz*pe_w1[128+hc];
        H[i] = fmaxf(h, 0.0f);
    }
    __syncthreads();

    int cg = t & 31, rg = t >> 5;
    int c0 = cg * 4, r0 = rg * 4;

    // ---- stage A: src = F@in_w + H@pe_w2 + biases (two fused streams) ----
    {
        u64 a01[4] = {0,0,0,0}, a23[4] = {0,0,0,0};
#pragma unroll 2
        for (int e0 = 0; e0 < 64; e0 += 4) {
            float4 af[4], ah[4];
#pragma unroll
            for (int r = 0; r < 4; r++) {
                af[r] = *(const float4*)(F + (r0+r)*DC + e0);
                ah[r] = *(const float4*)(H + (r0+r)*64 + e0);
            }
#pragma unroll
            for (int ee = 0; ee < 4; ee++) {
                double2 wi = __ldg((const double2*)(in_w  + (e0+ee)*DM + c0));
                double2 wp = __ldg((const double2*)(pe_w2 + (e0+ee)*DM + c0));
                u64 wi01 = __double_as_longlong(wi.x), wi23 = __double_as_longlong(wi.y);
                u64 wp01 = __double_as_longlong(wp.x), wp23 = __double_as_longlong(wp.y);
#pragma unroll
                for (int r = 0; r < 4; r++) {
                    float xf = (ee==0)?af[r].x:(ee==1)?af[r].y:(ee==2)?af[r].z:af[r].w;
                    float xh = (ee==0)?ah[r].x:(ee==1)?ah[r].y:(ee==2)?ah[r].z:ah[r].w;
                    u64 f2 = pk2(xf, xf), h2 = pk2(xh, xh);
                    fma2(a01[r], f2, wi01); fma2(a23[r], f2, wi23);
                    fma2(a01[r], h2, wp01); fma2(a23[r], h2, wp23);
                }
            }
        }
        float4 b1 = __ldg((const float4*)(in_b  + c0));
        float4 b2 = __ldg((const float4*)(pe_b2 + c0));
#pragma unroll
        for (int r = 0; r < 4; r++) {
            float v0,v1,v2,v3;
            upk2(a01[r], v0, v1); upk2(a23[r], v2, v3);
            float4 o = make_float4(v0+b1.x+b2.x, v1+b1.y+b2.y, v2+b1.z+b2.z, v3+b1.w+b2.w);
            S[(r0+r)*DM + c0+0] = o.x; S[(r0+r)*DM + c0+1] = o.y;
            S[(r0+r)*DM + c0+2] = o.z; S[(r0+r)*DM + c0+3] = o.w;
            *(float4*)(g_src + (row0+r0+r)*DM + c0) = o;
        }
    }
    __syncthreads();

    // ---- stage B: q/k/v, three fused weight streams ----
    {
        u64 q01[4]={0,0,0,0}, q23[4]={0,0,0,0};
        u64 k01[4]={0,0,0,0}, k23[4]={0,0,0,0};
        u64 v01[4]={0,0,0,0}, v23[4]={0,0,0,0};
#pragma unroll 2
        for (int e0 = 0; e0 < DM; e0 += 4) {
            float4 av[4];
#pragma unroll
            for (int r = 0; r < 4; r++)
                av[r] = *(const float4*)(S + (r0+r)*DM + e0);
#pragma unroll
            for (int ee = 0; ee < 4; ee++) {
                double2 wq = __ldg((const double2*)(qw + (e0+ee)*DM + c0));
                double2 wk = __ldg((const double2*)(kw + (e0+ee)*DM + c0));
                double2 wv = __ldg((const double2*)(vw + (e0+ee)*DM + c0));
                u64 q01w = __double_as_longlong(wq.x), q23w = __double_as_longlong(wq.y);
                u64 k01w = __double_as_longlong(wk.x), k23w = __double_as_longlong(wk.y);
                u64 v01w = __double_as_longlong(wv.x), v23w = __double_as_longlong(wv.y);
#pragma unroll
                for (int r = 0; r < 4; r++) {
                    float x = (ee==0)?av[r].x:(ee==1)?av[r].y:(ee==2)?av[r].z:av[r].w;
                    u64 a2 = pk2(x, x);
                    fma2(q01[r], a2, q01w); fma2(q23[r], a2, q23w);
                    fma2(k01[r], a2, k01w); fma2(k23[r], a2, k23w);
                    fma2(v01[r], a2, v01w); fma2(v23[r], a2, v23w);
                }
            }
        }
        float4 bq = __ldg((const float4*)(qb + c0));
        float4 bk = __ldg((const float4*)(kb + c0));
        float4 bv = __ldg((const float4*)(vb + c0));
#pragma unroll
        for (int r = 0; r < 4; r++) {
            int grow = row0 + r0 + r;
            float v0,v1,v2,v3;
            upk2(q01[r], v0, v1); upk2(q23[r], v2, v3);
            *(float4*)(g_q + grow*DM + c0) = make_float4(v0+bq.x, v1+bq.y, v2+bq.z, v3+bq.w);
            upk2(k01[r], v0, v1); upk2(k23[r], v2, v3);
            *(float4*)(g_k + grow*DM + c0) = make_float4(v0+bk.x, v1+bk.y, v2+bk.z, v3+bk.w);
            upk2(v01[r], v0, v1); upk2(v23[r], v2, v3);
            *(float4*)(g_v + grow*DM + c0) = make_float4(v0+bv.x, v1+bv.y, v2+bv.z, v3+bv.w);
        }
    }
}

// ---------------- attention (gather + interleaved-head softmax) ----------------
__global__ void k_attn(const float* __restrict__ kb, const float* __restrict__ vb) {
    int n = blockIdx.x;
    int t = threadIdx.x;           // 128
    int h = t >> 5, lane = t & 31;
    __shared__ float kp[MK][DM];
    __shared__ float vp[MK][DM];

    float kbv = __ldg(kb + t), vbv = __ldg(vb + t);
    int j0 = g_nbr[n*MK];
    float qv = (j0 >= 0) ? g_q[j0*DM + t] : 0.f;
#pragma unroll
    for (int m = 0; m < MK; m++) {
        int j = g_nbr[n*MK + m];
        kp[m][t] = (j >= 0) ? g_k[j*DM + t] : kbv;
        vp[m][t] = (j >= 0) ? g_v[j*DM + t] : vbv;
    }
    __syncthreads();

    float sc[MK];
#pragma unroll
    for (int m = 0; m < MK; m++) {
        float p = qv * kp[(h<<2) + (m>>2)][((m&3)<<5) + lane];
        sc[m] = warpAllSum(p) * 0.0883883476483184405f;  // 1/sqrt(128)
    }
    float mx = sc[0];
#pragma unroll
    for (int m = 1; m < MK; m++) mx = fmaxf(mx, sc[m]);
    float se = 0.f;
#pragma unroll
    for (int m = 0; m < MK; m++) { sc[m] = __expf(sc[m] - mx); se += sc[m]; }
    float inv = 1.f / se;
    float o = 0.f;
#pragma unroll
    for (int m = 0; m < MK; m++)
        o += sc[m] * inv * vp[(h<<2) + (m>>2)][((m&3)<<5) + lane];
    g_ho[n*DM + t] = o;
}

// ------- mega kernel: o-proj + LN1 + FFN1 + FFN2 + LN3 + fusion GEMM -------
__global__ __launch_bounds__(256)
void k_mega(const float* __restrict__ ow, const float* __restrict__ ob,
            const float* __restrict__ n1g, const float* __restrict__ n1b,
            const float* __restrict__ w1, const float* __restrict__ b1,
            const float* __restrict__ w2, const float* __restrict__ b2,
            const float* __restrict__ n3g, const float* __restrict__ n3b,
            const float* __restrict__ feat,
            const float* __restrict__ fw, const float* __restrict__ fb) {
    __shared__ float T[32*DM];
    __shared__ float U[32*DF];
    __shared__ float F[32*DC];
    int row0 = blockIdx.x * 32;
    int t = threadIdx.x;

    for (int i = t; i < 32*DM/4; i += 256)
        ((float4*)U)[i] = *(((const float4*)(g_ho + row0*DM)) + i);
    for (int i = t; i < 32*DC/4; i += 256)
        ((float4*)F)[i] = __ldg(((const float4*)(feat + row0*DC)) + i);
    __syncthreads();

    // ---- stage 1: out-proj + residual(src) + LN1 -> T ----
    {
        int cg = t & 31, rg = t >> 5;
        int c0 = cg*4, r0 = rg*4;
        u64 a01[4]={0,0,0,0}, a23[4]={0,0,0,0};
        gacc<4, DM, DM>(U + r0*DM, ow, DM, c0, a01, a23);
        float4 b  = __ldg((const float4*)(ob  + c0));
        float4 g4 = __ldg((const float4*)(n1g + c0));
        float4 bb = __ldg((const float4*)(n1b + c0));
#pragma unroll
        for (int r = 0; r < 4; r++) {
            float4 s = *(const float4*)(g_src + (row0+r0+r)*DM + c0);
            float v0,v1,v2,v3;
            upk2(a01[r], v0, v1); upk2(a23[r], v2, v3);
            v0 += b.x+s.x; v1 += b.y+s.y; v2 += b.z+s.z; v3 += b.w+s.w;
            float mean = warpAllSum(v0+v1+v2+v3) * (1.f/128.f);
            float d0=v0-mean, d1=v1-mean, d2=v2-mean, d3=v3-mean;
            float var = warpAllSum(d0*d0+d1*d1+d2*d2+d3*d3) * (1.f/128.f);
            float rs = rsqrtf(var + 1e-5f);
            float* tp = T + (r0+r)*DM + c0;
            tp[0]=d0*rs*g4.x+bb.x; tp[1]=d1*rs*g4.y+bb.y;
            tp[2]=d2*rs*g4.z+bb.z; tp[3]=d3*rs*g4.w+bb.w;
        }
    }
    __syncthreads();

    // ---- stage 2: FFN1 (128->256, relu) -> U ----
    {
        int cg = t & 63, rg = t >> 6;
        int c0 = cg*4, r0 = rg*8;
        u64 a01[8]={0,0,0,0,0,0,0,0}, a23[8]={0,0,0,0,0,0,0,0};
        gacc<8, DM, DM>(T + r0*DM, w1, DF, c0, a01, a23);
        float4 b = __ldg((const float4*)(b1 + c0));
#pragma unroll
        for (int r = 0; r < 8; r++) {
            float v0,v1,v2,v3;
            upk2(a01[r], v0, v1); upk2(a23[r], v2, v3);
            float* up = U + (r0+r)*DF + c0;
            up[0]=fmaxf(v0+b.x,0.f); up[1]=fmaxf(v1+b.y,0.f);
            up[2]=fmaxf(v2+b.z,0.f); up[3]=fmaxf(v3+b.w,0.f);
        }
    }
    __syncthreads();

    // ---- stage 3: FFN2 (256->128) + residual(T) + LN3 -> T ----
    {
        int cg = t & 31, rg = t >> 5;
        int c0 = cg*4, r0 = rg*4;
        u64 a01[4]={0,0,0,0}, a23[4]={0,0,0,0};
        gacc<4, DF, DF>(U + r0*DF, w2, DM, c0, a01, a23);
        float4 b  = __ldg((const float4*)(b2  + c0));
        float4 g4 = __ldg((const float4*)(n3g + c0));
        float4 bb = __ldg((const float4*)(n3b + c0));
        __syncthreads();   // U read done before T overwrite read hazard? (T rewritten below, read above in stage2 done)
#pragma unroll
        for (int r = 0; r < 4; r++) {
            float* tp = T + (r0+r)*DM + c0;
            float v0,v1,v2,v3;
            upk2(a01[r], v0, v1); upk2(a23[r], v2, v3);
            v0 += b.x+tp[0]; v1 += b.y+tp[1]; v2 += b.z+tp[2]; v3 += b.w+tp[3];
            float mean = warpAllSum(v0+v1+v2+v3) * (1.f/128.f);
            float d0=v0-mean, d1=v1-mean, d2=v2-mean, d3=v3-mean;
            float var = warpAllSum(d0*d0+d1*d1+d2*d2+d3*d3) * (1.f/128.f);
            float rs = rsqrtf(var + 1e-5f);
            tp[0]=d0*rs*g4.x+bb.x; tp[1]=d1*rs*g4.y+bb.y;
            tp[2]=d2*rs*g4.z+bb.z; tp[3]=d3*rs*g4.w+bb.w;
        }
    }
    __syncthreads();

    // ---- stage 4: fusion GEMM concat(F, T) @ fw + fb -> g_fused ----
    {
        int cg = t & 15, rg = t >> 4;
        int c0 = cg*4, r0 = rg*2;
        u64 a01[2]={0,0}, a23[2]={0,0};
        gacc<2, DC, DC>(F + r0*DC, fw, DC, c0, a01, a23);
        gacc<2, DM, DM>(T + r0*DM, fw + DC*DC, DC, c0, a01, a23);
        float4 b = __ldg((const float4*)(fb + c0));
#pragma unroll
        for (int r = 0; r < 2; r++) {
            float v0,v1,v2,v3;
            upk2(a01[r], v0, v1); upk2(a23[r], v2, v3);
            *(float4*)(g_fused + (row0+r0+r)*DC + c0) =
                make_float4(v0+b.x, v1+b.y, v2+b.z, v3+b.w);
        }
    }
}

// ---------------- batchnorm stats (train mode, biased var) ----------------
__global__ void k_stats(int N) {
    int c = blockIdx.x;             // 64 blocks
    int t = threadIdx.x;            // 256
    float s = 0.f, q = 0.f;
    for (int r = t; r < N; r += 256) {
        float v = g_fused[r*DC + c];
        s += v; q += v*v;
    }
    __shared__ float ss[256], sq[256];
    ss[t] = s; sq[t] = q; __syncthreads();
    for (int st = 128; st > 0; st >>= 1) {
        if (t < st) { ss[t] += ss[t+st]; sq[t] += sq[t+st]; }
        __syncthreads();
    }
    if (t == 0) {
        float mean = ss[0] / (float)N;
        g_mean[c] = mean;
        g_var[c]  = sq[0] / (float)N - mean*mean;
    }
}

__global__ void k_out(const float* __restrict__ bng, const float* __restrict__ bnb,
                      float* __restrict__ out, int total) {
    for (int i = blockIdx.x*blockDim.x + threadIdx.x; i < total; i += gridDim.x*blockDim.x) {
        int c = i & (DC-1);
        float v = g_fused[i];
        v = (v - g_mean[c]) * rsqrtf(g_var[c] + 1e-3f) * bng[c] + bnb[c];
        out[i] = fmaxf(v, 0.f);
    }
}

// ---------------- launch ----------------
extern "C" void kernel_launch(void* const* d_in, const int* in_sizes, int n_in,
                              void* d_out, int out_size) {
    const float* feat   = (const float*)d_in[0];
    const int*   coords = (const int*)  d_in[1];
    const float* pe_w1  = (const float*)d_in[2];
    const float* pe_b1  = (const float*)d_in[3];
    const float* pe_w2  = (const float*)d_in[4];
    const float* pe_b2  = (const float*)d_in[5];
    const float* in_w   = (const float*)d_in[6];
    const float* in_b   = (const float*)d_in[7];
    const float* q_w    = (const float*)d_in[8];
    const float* q_b    = (const float*)d_in[9];
    const float* k_w    = (const float*)d_in[10];
    const float* k_b    = (const float*)d_in[11];
    const float* v_w    = (const float*)d_in[12];
    const float* v_b    = (const float*)d_in[13];
    const float* o_w    = (const float*)d_in[14];
    const float* o_b    = (const float*)d_in[15];
    const float* n1_g   = (const float*)d_in[16];
    const float* n1_b   = (const float*)d_in[17];
    const float* l1_w   = (const float*)d_in[18];
    const float* l1_b   = (const float*)d_in[19];
    const float* l2_w   = (const float*)d_in[20];
    const float* l2_b   = (const float*)d_in[21];
    const float* n3_g   = (const float*)d_in[22];
    const float* n3_b   = (const float*)d_in[23];
    const float* fu_w   = (const float*)d_in[24];
    const float* fu_b   = (const float*)d_in[25];
    const float* bn_g   = (const float*)d_in[26];
    const float* bn_b   = (const float*)d_in[27];
    float* out = (float*)d_out;

    int N = in_sizes[0] / DC;   // 8192

    k_clear  <<<(NCELLS+1023)/1024, 1024>>>();
    k_scatter<<<(N+255)/256, 256>>>(coords, N);
    k_nbr    <<<(N+63)/64, 64>>>(coords, N);
    k_srcproj<<<N/32, 256>>>(feat, coords, pe_w1, pe_b1, pe_w2, pe_b2, in_w, in_b,
                             q_w, q_b, k_w, k_b, v_w, v_b);
    k_attn   <<<N, 128>>>(k_b, v_b);
    k_mega   <<<N/32, 256>>>(o_w, o_b, n1_g, n1_b, l1_w, l1_b, l2_w, l2_b,
                             n3_g, n3_b, feat, fu_w, fu_b);
    k_stats  <<<DC, 256>>>(N);
    k_out    <<<256, 256>>>(bn_g, bn_b, out, N*DC);
}